// round 9
// baseline (speedup 1.0000x reference)
#include <cuda_runtime.h>
#include <math.h>
#include <stdint.h>

#define PS 16
#define NB 32
#define IMG4 (1024*1024/4)       // float4 per image
#define TROW4 33                 // f4 row stride in tile (132 floats, padded)
#define TB4 (16*TROW4)           // f4 per batch slice = 528
#define TILE_BYTES (8*TB4*16)    // 67584 B dynamic smem

__device__ __forceinline__ float clamp01(float x) {
    return fminf(fmaxf(x, 0.0f), 1.0f);
}
__device__ __forceinline__ uint32_t smem_u32(const void* p) {
    uint32_t a;
    asm("{ .reg .u64 t; cvta.to.shared.u64 t, %1; cvt.u32.u64 %0, t; }"
        : "=r"(a) : "l"(p));
    return a;
}
__device__ __forceinline__ float ld_dsmem(uint32_t laddr, uint32_t rank) {
    uint32_t ra;
    asm("mapa.shared::cluster.u32 %0, %1, %2;" : "=r"(ra) : "r"(laddr), "r"(rank));
    float v;
    asm volatile("ld.shared::cluster.f32 %0, [%1];" : "=f"(v) : "r"(ra));
    return v;
}
#define CLUSTER_SYNC() do { \
    asm volatile("barrier.cluster.arrive.aligned;" ::: "memory"); \
    asm volatile("barrier.cluster.wait.aligned;"   ::: "memory"); \
} while (0)

// ---------------------------------------------------------------------------
// Cluster of 4 CTAs = one 16x128 strip (8 patches), all 32 batches.
// CTA rank r streams batches [8r,8r+8) of the strip into smem (contiguous
// 512B row reads), computes local per-patch partial stats, exchanges 16
// floats/rank via DSMEM, computes per-patch affine code, applies from smem.
// img read ONCE, in streaming order. 256 threads, 3 CTAs/SM.
// ---------------------------------------------------------------------------
__global__ void __launch_bounds__(256, 3) __cluster_dims__(4, 1, 1)
fused_kernel(const float4* __restrict__ img4,
             const float4* __restrict__ noise4,
             const float* __restrict__ r_strong,
             const float* __restrict__ r_drop,
             const float* __restrict__ r_else,
             const float* __restrict__ bright_f,
             const float* __restrict__ contrast_f,
             const float* __restrict__ slight_f,
             const int*   __restrict__ aug_choice,
             const int*   __restrict__ slight_choice,
             float4* __restrict__ out4) {
    extern __shared__ float4 tile[];          // [8][16][33]
    __shared__ float s_q[64], s_m[64];        // per (local b, patch)
    __shared__ float s_qpart[8], s_mpart[8];  // per patch, summed over 8 b
    __shared__ int   s_code[8];
    __shared__ float s_al[8], s_be[8], s_de[8];

    const int bx   = blockIdx.x;
    const int rank = bx & 3;                  // cluster rank = batch group
    const int str  = bx >> 2;                 // strip id 0..511
    const int sy   = str >> 3;                // patch row 0..63
    const int sxx  = str & 7;                 // col strip 0..7 (128 cols each)
    const int t    = threadIdx.x;
    const int c4   = t & 31;                  // f4 col in strip
    const int wr   = t >> 5;                  // row 0..7 (also row wr+8)
    const int gb0  = rank * 8;                // first global batch
    const int gcol4 = sxx * 32 + c4;

    // ---- Phase 1: stream 8 batch-copies of the strip into smem ----
#pragma unroll
    for (int pass = 0; pass < 2; ++pass) {
        const int row = wr + pass * 8;
        const int gr  = (sy * PS + row) * 256 + gcol4;
        float4 v[8];
#pragma unroll
        for (int b = 0; b < 8; ++b)
            v[b] = img4[(gb0 + b) * IMG4 + gr];
#pragma unroll
        for (int b = 0; b < 8; ++b)
            tile[b * TB4 + row * TROW4 + c4] = v[b];
    }
    __syncthreads();

    // ---- Phase 2: per-(b,patch) stats. unit u=(b,p), 4 threads each ----
    {
        const int u = t >> 2;                 // 0..63
        const int b = u >> 3;                 // local batch 0..7
        const int p = u & 7;                  // patch 0..7
        const int j = t & 3;                  // rows 4j..4j+3
        float s = 0.f, ss = 0.f;
#pragma unroll
        for (int k = 0; k < 4; ++k) {
#pragma unroll
            for (int m = 0; m < 4; ++m) {
                float4 x = tile[b * TB4 + (4 * j + k) * TROW4 + p * 4 + m];
                s  += (x.x + x.y) + (x.z + x.w);
                ss  = fmaf(x.x, x.x, ss);
                ss  = fmaf(x.y, x.y, ss);
                ss  = fmaf(x.z, x.z, ss);
                ss  = fmaf(x.w, x.w, ss);
            }
        }
#pragma unroll
        for (int off = 2; off >= 1; off >>= 1) {
            s  += __shfl_down_sync(0xffffffffu, s,  off, 4);
            ss += __shfl_down_sync(0xffffffffu, ss, off, 4);
        }
        if (j == 0) {
            float mean = s * (1.0f / 256.0f);
            float var  = (ss - s * s * (1.0f / 256.0f)) * (1.0f / 255.0f); // ddof=1
            var = fmaxf(var, 0.0f);
            float std_ = sqrtf(var);
            float iq   = 1.0f - 2.0f * fabsf(mean - 0.5f);
            s_q[u] = (std_ + iq + var) * (1.0f / 3.0f);
            s_m[u] = mean;
        }
    }
    __syncthreads();

    // ---- Phase 3a: local per-patch partials over this rank's 8 batches ----
    if (t < 8) {
        float qp = 0.f, mp = 0.f;
#pragma unroll
        for (int b = 0; b < 8; ++b) { qp += s_q[b * 8 + t]; mp += s_m[b * 8 + t]; }
        s_qpart[t] = qp;
        s_mpart[t] = mp;
    }
    CLUSTER_SYNC();

    // ---- Phase 3b: DSMEM exchange + code (all ranks compute identically) ----
    if (t < 8) {
        const uint32_t aq = smem_u32(&s_qpart[t]);
        const uint32_t am = smem_u32(&s_mpart[t]);
        float q = 0.f, m = 0.f;
#pragma unroll
        for (int r = 0; r < 4; ++r) {
            q += ld_dsmem(aq, r);
            m += ld_dsmem(am, r);
        }
        q *= (1.0f / NB);
        m *= (1.0f / NB);

        const int pg = sy * 64 + sxx * 8 + t;

        bool low    = q < 0.7f;
        bool strong = low  && (r_strong[pg] < 0.8f);
        bool drop   = low  && (q < 0.3f) && (r_drop[pg] < 0.1f);
        bool els    = !low && (r_else[pg] < 0.3f);

        int code = 0;
        if (strong) code = aug_choice[pg] + 1;      // 1..4
        if (els)    code = slight_choice[pg] + 5;   // 5..6
        if (drop)   code = 7;

        float alpha = 1.f, beta = 0.f, delta = 0.f;
        if      (code == 1) beta = 0.1f;
        else if (code == 3) alpha = bright_f[pg];
        else if (code == 4) { float cf = contrast_f[pg]; alpha = cf; delta = m * (1.0f - cf); }
        else if (code == 5) beta = 0.05f;
        else if (code == 6) alpha = slight_f[pg];
        else if (code == 7) alpha = 0.f;

        s_code[t] = code;
        s_al[t] = alpha; s_be[t] = beta; s_de[t] = delta;
    }
    CLUSTER_SYNC();   // peers' DSMEM reads done; also publishes s_code locally

    // ---- Phase 4: apply from smem, streaming float4 stores ----
    const int   p    = c4 >> 2;               // patch for this lane
    const int   code = s_code[p];
    const float al   = s_al[p];
    const float be   = s_be[p];
    const float de   = s_de[p];
    const float* tileF = (const float*)tile;

#pragma unroll
    for (int pass = 0; pass < 2; ++pass) {
        const int row = wr + pass * 8;
        const int gr  = (sy * PS + row) * 256 + gcol4;

        if (code == 2) {
            // 3x3 zero-padded blur confined to the patch, from smem.
#pragma unroll 2
            for (int b = 0; b < 8; ++b) {
                const float* tb = tileF + b * (TB4 * 4);
                float rs[4];
#pragma unroll
                for (int j = 0; j < 4; ++j) {
                    const int colf = c4 * 4 + j;
                    const int lc   = colf & 15;
                    float sum = 0.f;
#pragma unroll
                    for (int dy = -1; dy <= 1; ++dy) {
                        const int rr = row + dy;
                        if (rr < 0 || rr >= PS) continue;
#pragma unroll
                        for (int dx = -1; dx <= 1; ++dx) {
                            const int cc = lc + dx;
                            if (cc < 0 || cc >= PS) continue;
                            sum += tb[rr * 132 + colf + dx];
                        }
                    }
                    rs[j] = sum * (1.0f / 9.0f);
                }
                __stcs(&out4[(gb0 + b) * IMG4 + gr],
                       make_float4(rs[0], rs[1], rs[2], rs[3]));
            }
        } else if (be != 0.0f) {
#pragma unroll
            for (int b0 = 0; b0 < 8; b0 += 4) {
                float4 vv[4], nn[4];
#pragma unroll
                for (int k = 0; k < 4; ++k) {
                    vv[k] = tile[(b0 + k) * TB4 + row * TROW4 + c4];
                    nn[k] = noise4[(gb0 + b0 + k) * IMG4 + gr];
                }
#pragma unroll
                for (int k = 0; k < 4; ++k) {
                    float4 r;
                    r.x = clamp01(fmaf(be, nn[k].x, fmaf(al, vv[k].x, de)));
                    r.y = clamp01(fmaf(be, nn[k].y, fmaf(al, vv[k].y, de)));
                    r.z = clamp01(fmaf(be, nn[k].z, fmaf(al, vv[k].z, de)));
                    r.w = clamp01(fmaf(be, nn[k].w, fmaf(al, vv[k].w, de)));
                    __stcs(&out4[(gb0 + b0 + k) * IMG4 + gr], r);
                }
            }
        } else {
#pragma unroll
            for (int b = 0; b < 8; ++b) {
                float4 v = tile[b * TB4 + row * TROW4 + c4];
                float4 r;
                r.x = clamp01(fmaf(al, v.x, de));
                r.y = clamp01(fmaf(al, v.y, de));
                r.z = clamp01(fmaf(al, v.z, de));
                r.w = clamp01(fmaf(al, v.w, de));
                __stcs(&out4[(gb0 + b) * IMG4 + gr], r);
            }
        }
    }
}

extern "C" void kernel_launch(void* const* d_in, const int* in_sizes, int n_in,
                              void* d_out, int out_size) {
    const float4* img4         = (const float4*)d_in[0];
    const float4* noise4       = (const float4*)d_in[1];
    const float* r_strong      = (const float*)d_in[2];
    const float* r_drop        = (const float*)d_in[3];
    const float* r_else        = (const float*)d_in[4];
    const float* bright_f      = (const float*)d_in[5];
    const float* contrast_f    = (const float*)d_in[6];
    const float* slight_f      = (const float*)d_in[7];
    const int*   aug_choice    = (const int*)d_in[8];
    const int*   slight_choice = (const int*)d_in[9];
    float4* out4 = (float4*)d_out;

    cudaFuncSetAttribute(fused_kernel,
                         cudaFuncAttributeMaxDynamicSharedMemorySize,
                         TILE_BYTES);

    // 512 strips x 4 cluster CTAs
    fused_kernel<<<2048, 256, TILE_BYTES>>>(img4, noise4, r_strong, r_drop,
                                            r_else, bright_f, contrast_f,
                                            slight_f, aug_choice,
                                            slight_choice, out4);
}

// round 10
// speedup vs baseline: 1.2508x; 1.2508x over previous
#include <cuda_runtime.h>
#include <math.h>
#include <stdint.h>

#define PS 16
#define NB 32
#define IMGSZ (1024*1024)
#define BSTRIDE 260                 // floats per batch slice (1040 B, 16B aligned)
#define SLOT_FLOATS (NB*BSTRIDE)    // 8320 floats = 33280 B
#define TILE_BYTES (2*SLOT_FLOATS*4)

__device__ __forceinline__ float clamp01(float x) {
    return fminf(fmaxf(x, 0.0f), 1.0f);
}
__device__ __forceinline__ uint32_t smem_u32(const void* p) {
    uint32_t a;
    asm("{ .reg .u64 t; cvta.to.shared.u64 t, %1; cvt.u32.u64 %0, t; }"
        : "=r"(a) : "l"(p));
    return a;
}
__device__ __forceinline__ void cp_async16(uint32_t dst, const float* src) {
    asm volatile("cp.async.cg.shared.global [%0], [%1], 16;"
                 :: "r"(dst), "l"(src));
}
#define CP_COMMIT() asm volatile("cp.async.commit_group;" ::: "memory")

// ---------------------------------------------------------------------------
// One CTA pipelines 4 patches (same patch-row, adjacent cols) through a
// 2-slot cp.async smem buffer. 256 threads. Per stage:
//   issue: 8 x 16B LDGSTS per thread (no register staging)
//   stats: thread (b=t>>3, j=t&7) sums cols 2j,2j+1 over 16 rows, shfl-8
//   code : thread 0 -> affine (alpha,beta,delta) / blur flag
//   apply: thread (r=t>>4, c=t&15) iterates 32 batches, conflict-free LDS,
//          streaming scalar stores; noise LDG only when beta != 0.
// While stage i computes, stages i+1/i+2 loads are in flight -> DRAM stays
// busy through the compute phases (duty-cycle fix for R5..R9).
// ---------------------------------------------------------------------------
__global__ void __launch_bounds__(256, 3)
fused_kernel(const float* __restrict__ img,
             const float* __restrict__ noise,
             const float* __restrict__ r_strong,
             const float* __restrict__ r_drop,
             const float* __restrict__ r_else,
             const float* __restrict__ bright_f,
             const float* __restrict__ contrast_f,
             const float* __restrict__ slight_f,
             const int*   __restrict__ aug_choice,
             const int*   __restrict__ slight_choice,
             float* __restrict__ out) {
    extern __shared__ float tile[];          // 2 slots x [32][16][16+pad]
    __shared__ float s_q[NB], s_m[NB];
    __shared__ int   s_code;
    __shared__ float s_al, s_be, s_de;

    const int ct = blockIdx.x;               // 0..1023
    const int t  = threadIdx.x;

    // per-thread constant decomposition for cp.async issue
    const int rem  = t & 63;                 // chunk within batch-quad
    const int lrow = rem >> 2;               // row 0..15
    const int lc4  = rem & 3;                // 16B chunk in row
    const int bofs = t >> 6;                 // 0..3
    const uint32_t tile_u32 = smem_u32(tile);

    const int p0 = ct * 4;                   // first patch (same sy for all 4)
    const int sy = p0 >> 6;

    // issue loads for patch (p0+s) into slot (s&1)
    auto issue = [&](int s) {
        const int px   = (p0 + s) & 63;
        const float* src0 = img + ((sy * PS + lrow) * 1024 + px * PS + lc4 * 4);
        uint32_t dst0 = tile_u32 + (uint32_t)(s & 1) * (SLOT_FLOATS * 4)
                      + (uint32_t)(bofs * (BSTRIDE * 4) + lrow * 64 + lc4 * 16);
#pragma unroll
        for (int k = 0; k < 8; ++k) {
            const int b = k * 4 + bofs;
            cp_async16(dst0 + (uint32_t)(k * 4) * (BSTRIDE * 4),
                       src0 + (size_t)b * IMGSZ);
        }
        CP_COMMIT();
    };

    issue(0);
    issue(1);

    const int r = t >> 4;                    // apply row
    const int c = t & 15;                    // apply col

#pragma unroll
    for (int s = 0; s < 4; ++s) {
        if (s < 3) asm volatile("cp.async.wait_group 1;" ::: "memory");
        else       asm volatile("cp.async.wait_group 0;" ::: "memory");
        __syncthreads();

        float* slot = tile + (s & 1) * SLOT_FLOATS;
        const int px = (p0 + s) & 63;
        const int pg = sy * 64 + px;

        // ---- stats: thread (b, j) sums cols 2j,2j+1 over all 16 rows ----
        {
            const int b = t >> 3;
            const int j = t & 7;
            const float* base = slot + b * BSTRIDE + 2 * j;
            float sm = 0.f, ss = 0.f;
#pragma unroll
            for (int rr = 0; rr < PS; ++rr) {
                float x0 = base[rr * 16];
                float x1 = base[rr * 16 + 1];
                sm += x0 + x1;
                ss  = fmaf(x0, x0, ss);
                ss  = fmaf(x1, x1, ss);
            }
#pragma unroll
            for (int off = 4; off >= 1; off >>= 1) {
                sm += __shfl_down_sync(0xffffffffu, sm, off, 8);
                ss += __shfl_down_sync(0xffffffffu, ss, off, 8);
            }
            if (j == 0) {
                float mean = sm * (1.0f / 256.0f);
                float var  = (ss - sm * sm * (1.0f / 256.0f)) * (1.0f / 255.0f);
                var = fmaxf(var, 0.0f);
                float std_ = sqrtf(var);
                float iq   = 1.0f - 2.0f * fabsf(mean - 0.5f);
                s_q[b] = (std_ + iq + var) * (1.0f / 3.0f);
                s_m[b] = mean;
            }
        }
        __syncthreads();

        // ---- code (thread 0) ----
        if (t == 0) {
            float q = 0.f, m = 0.f;
#pragma unroll
            for (int b = 0; b < NB; ++b) { q += s_q[b]; m += s_m[b]; }
            q *= (1.0f / NB);
            m *= (1.0f / NB);

            bool low    = q < 0.7f;
            bool strong = low  && (r_strong[pg] < 0.8f);
            bool drop   = low  && (q < 0.3f) && (r_drop[pg] < 0.1f);
            bool els    = !low && (r_else[pg] < 0.3f);

            int code = 0;
            if (strong) code = aug_choice[pg] + 1;
            if (els)    code = slight_choice[pg] + 5;
            if (drop)   code = 7;

            float alpha = 1.f, beta = 0.f, delta = 0.f;
            if      (code == 1) beta = 0.1f;
            else if (code == 3) alpha = bright_f[pg];
            else if (code == 4) { float cf = contrast_f[pg]; alpha = cf; delta = m * (1.0f - cf); }
            else if (code == 5) beta = 0.05f;
            else if (code == 6) alpha = slight_f[pg];
            else if (code == 7) alpha = 0.f;

            s_code = code; s_al = alpha; s_be = beta; s_de = delta;
        }
        __syncthreads();

        const int   code = s_code;           // CTA-uniform
        const float al   = s_al;
        const float be   = s_be;
        const float de   = s_de;

        const int gbase = (sy * PS + r) * 1024 + px * PS + c;
        const float* tb0 = slot + r * 16 + c;

        if (code == 2) {
            // 3x3 zero-padded blur from smem (slot bounds = patch bounds)
#pragma unroll 4
            for (int b = 0; b < NB; ++b) {
                const float* tb = slot + b * BSTRIDE;
                float sum = 0.f;
#pragma unroll
                for (int dy = -1; dy <= 1; ++dy) {
                    const int rr = r + dy;
                    if (rr < 0 || rr >= PS) continue;
#pragma unroll
                    for (int dx = -1; dx <= 1; ++dx) {
                        const int cc = c + dx;
                        if (cc < 0 || cc >= PS) continue;
                        sum += tb[rr * 16 + cc];
                    }
                }
                __stcs(&out[gbase + (size_t)b * IMGSZ], sum * (1.0f / 9.0f));
            }
        } else if (be != 0.0f) {
#pragma unroll 8
            for (int b = 0; b < NB; ++b) {
                float v = tb0[b * BSTRIDE];
                float n = noise[gbase + (size_t)b * IMGSZ];
                __stcs(&out[gbase + (size_t)b * IMGSZ],
                       clamp01(fmaf(be, n, fmaf(al, v, de))));
            }
        } else {
#pragma unroll 8
            for (int b = 0; b < NB; ++b) {
                float v = tb0[b * BSTRIDE];
                __stcs(&out[gbase + (size_t)b * IMGSZ],
                       clamp01(fmaf(al, v, de)));
            }
        }

        if (s < 2) {
            __syncthreads();                  // everyone done reading this slot
            issue(s + 2);                     // refill it
        }
    }
}

extern "C" void kernel_launch(void* const* d_in, const int* in_sizes, int n_in,
                              void* d_out, int out_size) {
    const float* img           = (const float*)d_in[0];
    const float* noise         = (const float*)d_in[1];
    const float* r_strong      = (const float*)d_in[2];
    const float* r_drop        = (const float*)d_in[3];
    const float* r_else        = (const float*)d_in[4];
    const float* bright_f      = (const float*)d_in[5];
    const float* contrast_f    = (const float*)d_in[6];
    const float* slight_f      = (const float*)d_in[7];
    const int*   aug_choice    = (const int*)d_in[8];
    const int*   slight_choice = (const int*)d_in[9];
    float* out = (float*)d_out;

    cudaFuncSetAttribute(fused_kernel,
                         cudaFuncAttributeMaxDynamicSharedMemorySize,
                         TILE_BYTES);

    fused_kernel<<<1024, 256, TILE_BYTES>>>(img, noise, r_strong, r_drop,
                                            r_else, bright_f, contrast_f,
                                            slight_f, aug_choice,
                                            slight_choice, out);
}